// round 16
// baseline (speedup 1.0000x reference)
#include <cuda_runtime.h>
#include <math.h>
#include <stdint.h>

#define B_   64
#define T_   20
#define N_   100
#define F_   64
#define H_   256
#define BT_  (B_*T_)        // 1280
#define BTN_ (B_*T_*N_)     // 128000
#define NP_  128            // padded node count (M side)
#define KP_  112            // padded node count (K side, 7x16)
#define LN_EPS 1e-5f

typedef unsigned long long u64;

// ---------------- f32x2 packed-math helpers (sm_103a) ----------------------
__device__ __forceinline__ u64 fma2(u64 a, u64 b, u64 c) {
    u64 d;
    asm("fma.rn.f32x2 %0, %1, %2, %3;" : "=l"(d) : "l"(a), "l"(b), "l"(c));
    return d;
}
__device__ __forceinline__ u64 dup2(float x) {
    u64 d;
    asm("mov.b64 %0, {%1, %1};" : "=l"(d) : "f"(x));
    return d;
}
__device__ __forceinline__ float2 unpack2(u64 v) {
    float2 r;
    asm("mov.b64 {%0, %1}, %2;" : "=f"(r.x), "=f"(r.y) : "l"(v));
    return r;
}

// ---------------- cp.async helpers -----------------------------------------
__device__ __forceinline__ void cp_async16(uint32_t sa, const void* gp) {
    asm volatile("cp.async.ca.shared.global [%0], [%1], 16;" :: "r"(sa), "l"(gp));
}
__device__ __forceinline__ void cp_commit() {
    asm volatile("cp.async.commit_group;");
}
__device__ __forceinline__ void cp_wait0() {
    asm volatile("cp.async.wait_group 0;");
}

// ---------------- scratch (static device globals; no allocation) ----------
__device__ float g_m   [N_*BT_*H_];      // msg / attn scratch
__device__ float g_h0  [NP_*BT_*H_];     // node-padded rows stay zero
__device__ float g_h1  [NP_*BT_*H_];
__device__ float g_qv  [BTN_*H_];        // q' = h @ (Wq Wk^T)
__device__ float g_adjp[NP_*KP_];        // zero-padded adjacency [128][112]
__device__ float g_wkt [H_*H_];          // Wk^T
__device__ float g_mqk [H_*H_];          // Wq @ Wk^T
__device__ float g_wvp [H_*H_];          // Wv @ Wp
__device__ float g_u   [H_];             // Wk @ bq
__device__ float g_bvp [H_];             // bv @ Wp + bp

// ---------------- merged misc prep ----------------------------------------
__global__ void prep_misc(const float* __restrict__ adj,
                          const float* __restrict__ Wk,
                          const float* __restrict__ bq,
                          const float* __restrict__ bv,
                          const float* __restrict__ Wp,
                          const float* __restrict__ bp,
                          float* __restrict__ adjp, float* __restrict__ wkt,
                          float* __restrict__ u, float* __restrict__ bvp) {
    const int tid = threadIdx.x;
    const int blk = blockIdx.x;
    if (blk < 56) {
        int i = blk * 256 + tid;                  // 128*112 = 14336
        if (i < NP_*KP_) {
            int n = i / KP_, m2 = i - n * KP_;
            adjp[i] = (n < N_ && m2 < N_) ? adj[n * N_ + m2] : 0.f;
        }
    } else if (blk < 312) {
        int i = (blk - 56) * 256 + tid;           // 65536
        int o = i >> 8, g = i & 255;
        wkt[i] = Wk[g * H_ + o];
    } else if (blk < 344) {
        const int g = (blk - 312) * 8 + (tid >> 5);
        const int lane = tid & 31;
        float s = 0.f;
#pragma unroll
        for (int i = 0; i < 8; i++) {
            int o = lane + 32 * i;
            s = fmaf(Wk[g * H_ + o], bq[o], s);
        }
#pragma unroll
        for (int off = 16; off; off >>= 1)
            s += __shfl_xor_sync(0xffffffffu, s, off);
        if (lane == 0) u[g] = s;
    } else {
        const int o = tid;
        float s0 = bp[o], s1 = 0.f, s2 = 0.f, s3 = 0.f;
        for (int f = 0; f < H_; f += 4) {
            s0 = fmaf(bv[f+0], Wp[(f+0) * H_ + o], s0);
            s1 = fmaf(bv[f+1], Wp[(f+1) * H_ + o], s1);
            s2 = fmaf(bv[f+2], Wp[(f+2) * H_ + o], s2);
            s3 = fmaf(bv[f+3], Wp[(f+3) * H_ + o], s3);
        }
        bvp[o] = (s0 + s1) + (s2 + s3);
    }
}

// ---------------- msg SGEMM: 128 threads, 16x8 tile, f32x2 core ------------
// C[M,Nn] = A[M,K] @ B[K,Nn]. MG: row store guard. XB: B is x in [bt,n,f]
// layout read on the fly as B[k=n][c=bt*64+f] (rows clamped to n<100; the
// corresponding adj columns are zero so clamped values are never used).
template<bool MG, bool XB>
__global__ void __launch_bounds__(128, 2) sgemm_kernel(
    const float* __restrict__ A, const float* __restrict__ Bm,
    float* __restrict__ C, int M, int Nn, int K, int Mvalid) {
    __shared__ __align__(16) float As[2][16][132];
    __shared__ __align__(16) float Bs[2][16][128];

    const int tid = threadIdx.x;
    const int bx = blockIdx.x;
    const int arow = tid;                              // one A row per thread
    const int brow = tid >> 5, bcol = (tid & 31) << 2; // B: 4 rows per pass
    const int tx = tid & 15, ty = tid >> 4;

    const float* Ap = A + (size_t)arow * K;            // M=128 single tile
    // B base + row stride
    const float* Bbase;
    size_t brs;
    if (XB) {
        int gc = bx * 128 + bcol;
        int bt = gc >> 6, f = gc & 63;
        Bbase = Bm + (size_t)bt * N_ * F_ + f;
        brs = F_;
    } else {
        Bbase = Bm + (size_t)bx * 128 + bcol;
        brs = (size_t)Nn;
    }

    uint32_t bdst0 = (uint32_t)__cvta_generic_to_shared(&Bs[0][brow][bcol]);
    uint32_t bdst1 = (uint32_t)__cvta_generic_to_shared(&Bs[1][brow][bcol]);

    u64 acc[16][4];
#pragma unroll
    for (int i = 0; i < 16; i++)
#pragma unroll
        for (int j = 0; j < 4; j++) acc[i][j] = 0ull;

    // prologue
    {
#pragma unroll
        for (int c = 0; c < 4; c++) {
            float4 av = *(const float4*)(Ap + c * 4);
            As[0][c*4+0][arow] = av.x;
            As[0][c*4+1][arow] = av.y;
            As[0][c*4+2][arow] = av.z;
            As[0][c*4+3][arow] = av.w;
        }
#pragma unroll
        for (int i = 0; i < 4; i++) {
            int row = brow + i * 4;
            if (XB && row >= N_) row = 0;   // clamped; multiplied by adj zeros
            cp_async16(bdst0 + i * 4 * 128 * 4, Bbase + (size_t)row * brs);
        }
        cp_commit();
        cp_wait0();
    }
    __syncthreads();

    int buf = 0;
    for (int k0 = 16; k0 <= K; k0 += 16) {
        const bool more = (k0 < K);
        float4 av[4];
        if (more) {
#pragma unroll
            for (int c = 0; c < 4; c++)
                av[c] = *(const float4*)(Ap + k0 + c * 4);
            uint32_t bd = buf ? bdst0 : bdst1;
#pragma unroll
            for (int i = 0; i < 4; i++) {
                int row = k0 + brow + i * 4;
                if (XB && row >= N_) row = 0;
                cp_async16(bd + i * 4 * 128 * 4, Bbase + (size_t)row * brs);
            }
            cp_commit();
        }

        const float (*Asb)[132] = As[buf];
        const float (*Bsb)[128] = Bs[buf];
#pragma unroll
        for (int kk = 0; kk < 16; kk++) {
            float a[16];
            *(float4*)(a)    = *(const float4*)&Asb[kk][ty*16];
            *(float4*)(a+4)  = *(const float4*)&Asb[kk][ty*16+4];
            *(float4*)(a+8)  = *(const float4*)&Asb[kk][ty*16+8];
            *(float4*)(a+12) = *(const float4*)&Asb[kk][ty*16+12];
            ulonglong2 bp0 = *(const ulonglong2*)&Bsb[kk][tx*4];
            ulonglong2 bp1 = *(const ulonglong2*)&Bsb[kk][64 + tx*4];
            u64 b2[4] = { bp0.x, bp0.y, bp1.x, bp1.y };
#pragma unroll
            for (int i = 0; i < 16; i++) {
                u64 ad = dup2(a[i]);
#pragma unroll
                for (int j = 0; j < 4; j++)
                    acc[i][j] = fma2(ad, b2[j], acc[i][j]);
            }
        }

        if (more) {
            const int nb = buf ^ 1;
#pragma unroll
            for (int c = 0; c < 4; c++) {
                As[nb][c*4+0][arow] = av[c].x;
                As[nb][c*4+1][arow] = av[c].y;
                As[nb][c*4+2][arow] = av[c].z;
                As[nb][c*4+3][arow] = av[c].w;
            }
            cp_wait0();
            __syncthreads();
            buf = nb;
        }
    }

    const int crow0 = ty * 16;
    const int c0 = bx * 128 + tx * 4;
#pragma unroll
    for (int i = 0; i < 16; i++) {
        if (MG && (crow0 + i) >= Mvalid) continue;
        size_t rbase = (size_t)(crow0 + i) * Nn;
#pragma unroll
        for (int g = 0; g < 2; g++) {
            const int col = c0 + g * 64;
            float2 p0 = unpack2(acc[i][g*2 + 0]);
            float2 p1 = unpack2(acc[i][g*2 + 1]);
            float4 o;
            o.x = p0.x; o.y = p0.y; o.z = p1.x; o.w = p1.y;
            *(float4*)(C + rbase + col) = o;
        }
    }
}

// ---------------- dense GEMM: 256 threads, 128x256 CTA tile ----------------
// C[M,256] = A[M,K] @ B[K,256] (+bias)(relu)(+res | LN+scatter).
// Thread tile 8 rows x 16 cols (cols tx*4 + g*64, g=0..3). A read ONCE.
#define DA_STR 132
#define DA_SZ  (16*DA_STR)     // per-buffer A floats
#define DB_SZ  (16*256)
#define DSMEM  ((2*DA_SZ + 2*DB_SZ)*4)   // 49664 B

template<bool BIAS, bool RELU, bool RES, bool LN>
__global__ void __launch_bounds__(256) dgemm_kernel(
    const float* __restrict__ A, const float* __restrict__ Bm,
    const float* __restrict__ bias, const float* __restrict__ res,
    const float* __restrict__ gamma, const float* __restrict__ beta,
    float* __restrict__ C, int K) {
    extern __shared__ __align__(16) float dsm[];
    float* Asm = dsm;                 // [2][16][132]
    float* Bsm = dsm + 2*DA_SZ;       // [2][16][256]

    const int tid = threadIdx.x;
    const int by = blockIdx.x;
    const int arow = tid >> 1, acol = (tid & 1) << 3;
    const int brow = tid >> 4, bcol = (tid & 15) << 4;
    const int tx = tid & 15, ty = tid >> 4;

    const float* Ap = A + ((size_t)by * 128 + arow) * K + acol;
    const float* Bp = Bm + (size_t)brow * 256 + bcol;

    uint32_t bdst0 = (uint32_t)__cvta_generic_to_shared(Bsm + brow*256 + bcol);
    uint32_t bdst1 = (uint32_t)__cvta_generic_to_shared(Bsm + DB_SZ + brow*256 + bcol);

    u64 acc[8][8];
#pragma unroll
    for (int i = 0; i < 8; i++)
#pragma unroll
        for (int j = 0; j < 8; j++) acc[i][j] = 0ull;

    // prologue
    {
        float4 av0 = *(const float4*)(Ap);
        float4 av1 = *(const float4*)(Ap + 4);
        float* Ad = Asm;
        Ad[(acol+0)*DA_STR + arow] = av0.x;
        Ad[(acol+1)*DA_STR + arow] = av0.y;
        Ad[(acol+2)*DA_STR + arow] = av0.z;
        Ad[(acol+3)*DA_STR + arow] = av0.w;
        Ad[(acol+4)*DA_STR + arow] = av1.x;
        Ad[(acol+5)*DA_STR + arow] = av1.y;
        Ad[(acol+6)*DA_STR + arow] = av1.z;
        Ad[(acol+7)*DA_STR + arow] = av1.w;
#pragma unroll
        for (int c = 0; c < 4; c++)
            cp_async16(bdst0 + c * 16, Bp + c * 4);
        cp_commit();
        cp_wait0();
    }
    __syncthreads();

    int buf = 0;
    for (int k0 = 16; k0 <= K; k0 += 16) {
        const bool more = (k0 < K);
        float4 av0, av1;
        if (more) {
            av0 = *(const float4*)(Ap + k0);
            av1 = *(const float4*)(Ap + k0 + 4);
            uint32_t bd = buf ? bdst0 : bdst1;
            const float* bsrc = Bp + (size_t)k0 * 256;
#pragma unroll
            for (int c = 0; c < 4; c++)
                cp_async16(bd + c * 16, bsrc + c * 4);
            cp_commit();
        }

        const float* Ab = Asm + buf * DA_SZ;
        const float* Bb = Bsm + buf * DB_SZ;
#pragma unroll
        for (int kk = 0; kk < 16; kk++) {
            float a[8];
            *(float4*)(a)   = *(const float4*)(Ab + kk*DA_STR + ty*8);
            *(float4*)(a+4) = *(const float4*)(Ab + kk*DA_STR + ty*8 + 4);
            u64 b2[8];
#pragma unroll
            for (int g = 0; g < 4; g++) {
                ulonglong2 bp2 = *(const ulonglong2*)(Bb + kk*256 + g*64 + tx*4);
                b2[g*2+0] = bp2.x;
                b2[g*2+1] = bp2.y;
            }
#pragma unroll
            for (int i = 0; i < 8; i++) {
                u64 ad = dup2(a[i]);
#pragma unroll
                for (int j = 0; j < 8; j++)
                    acc[i][j] = fma2(ad, b2[j], acc[i][j]);
            }
        }

        if (more) {
            const int nb = buf ^ 1;
            float* Ad = Asm + nb * DA_SZ;
            Ad[(acol+0)*DA_STR + arow] = av0.x;
            Ad[(acol+1)*DA_STR + arow] = av0.y;
            Ad[(acol+2)*DA_STR + arow] = av0.z;
            Ad[(acol+3)*DA_STR + arow] = av0.w;
            Ad[(acol+4)*DA_STR + arow] = av1.x;
            Ad[(acol+5)*DA_STR + arow] = av1.y;
            Ad[(acol+6)*DA_STR + arow] = av1.z;
            Ad[(acol+7)*DA_STR + arow] = av1.w;
            cp_wait0();
            __syncthreads();
            buf = nb;
        }
    }

    // epilogue: rows ty*8+i, cols tx*4 + g*64 (g=0..3)
    float4 gam[4], bet[4];
    if (LN) {
#pragma unroll
        for (int g = 0; g < 4; g++) {
            gam[g] = *(const float4*)(gamma + g*64 + tx*4);
            bet[g] = *(const float4*)(beta  + g*64 + tx*4);
        }
    }
#pragma unroll
    for (int i = 0; i < 8; i++) {
        const int grow = by * 128 + ty * 8 + i;
        float v[16];
#pragma unroll
        for (int g = 0; g < 4; g++) {
            float2 p0 = unpack2(acc[i][g*2 + 0]);
            float2 p1 = unpack2(acc[i][g*2 + 1]);
            v[g*4+0] = p0.x; v[g*4+1] = p0.y;
            v[g*4+2] = p1.x; v[g*4+3] = p1.y;
            if (BIAS) {
                const float* bb = bias + g*64 + tx*4;
                v[g*4+0] += bb[0]; v[g*4+1] += bb[1];
                v[g*4+2] += bb[2]; v[g*4+3] += bb[3];
            }
            if (RELU) {
#pragma unroll
                for (int e = 0; e < 4; e++)
                    v[g*4+e] = fmaxf(v[g*4+e], 0.f);
            }
            if (RES) {
                float4 r = *(const float4*)(res + (size_t)grow*256 + g*64 + tx*4);
                v[g*4+0] += r.x; v[g*4+1] += r.y;
                v[g*4+2] += r.z; v[g*4+3] += r.w;
            }
        }
        if (LN) {
            // half-warp (16 lanes of this row) butterfly reduction
            float s = 0.f;
#pragma unroll
            for (int l = 0; l < 16; l++) s += v[l];
#pragma unroll
            for (int off = 8; off; off >>= 1)
                s += __shfl_xor_sync(0xffffffffu, s, off);
            float mean = s * (1.f / H_);
            float sq = 0.f;
#pragma unroll
            for (int l = 0; l < 16; l++) {
                float d = v[l] - mean;
                sq = fmaf(d, d, sq);
            }
#pragma unroll
            for (int off = 8; off; off >>= 1)
                sq += __shfl_xor_sync(0xffffffffu, sq, off);
            float rstd = rsqrtf(sq * (1.f / H_) + LN_EPS);
            // scatter: row grow = n*BT + bt  ->  out[(bt*N + n)*H + col]
            const int n = grow / BT_, bt = grow - n * BT_;
            float* op = C + ((size_t)bt * N_ + n) * H_;
#pragma unroll
            for (int g = 0; g < 4; g++) {
                float4 o;
                o.x = (v[g*4+0] - mean) * rstd * gam[g].x + bet[g].x;
                o.y = (v[g*4+1] - mean) * rstd * gam[g].y + bet[g].y;
                o.z = (v[g*4+2] - mean) * rstd * gam[g].z + bet[g].z;
                o.w = (v[g*4+3] - mean) * rstd * gam[g].w + bet[g].w;
                *(float4*)(op + g*64 + tx*4) = o;
            }
        } else {
            float* cp = C + (size_t)grow * 256;
#pragma unroll
            for (int g = 0; g < 4; g++) {
                float4 o;
                o.x = v[g*4+0]; o.y = v[g*4+1];
                o.z = v[g*4+2]; o.w = v[g*4+3];
                *(float4*)(cp + g*64 + tx*4) = o;
            }
        }
    }
}

// fused prep GEMM (256-thread body, tiny): z=0 -> mqk, z=1 -> wvp
__global__ void __launch_bounds__(256, 2) prep_gemm(
    const float* __restrict__ Wq, const float* __restrict__ wkt,
    const float* __restrict__ Wv, const float* __restrict__ Wp,
    float* __restrict__ mqk, float* __restrict__ wvp) {
    __shared__ __align__(16) float As[2][16][132];
    __shared__ __align__(16) float Bs[2][16][128];

    const float* A  = blockIdx.z ? Wv : Wq;
    const float* Bm = blockIdx.z ? Wp : wkt;
    float* C        = blockIdx.z ? wvp : mqk;
    const int Nn = H_, K = H_;

    const int tid = threadIdx.x;
    const int bx = blockIdx.x, by = blockIdx.y;
    const int arow = tid >> 1, acol = (tid & 1) << 3;
    const int brow = tid >> 4, bcol = (tid & 15) << 3;
    const int tx = tid & 15, ty = tid >> 4;

    const float* Ap = A + ((size_t)by * 128 + arow) * K + acol;
    const float* Bp = Bm + (size_t)brow * Nn + (size_t)bx * 128 + bcol;

    uint32_t bdst0 = (uint32_t)__cvta_generic_to_shared(&Bs[0][brow][bcol]);
    uint32_t bdst1 = (uint32_t)__cvta_generic_to_shared(&Bs[1][brow][bcol]);

    u64 acc[8][4];
#pragma unroll
    for (int i = 0; i < 8; i++)
#pragma unroll
        for (int j = 0; j < 4; j++) acc[i][j] = 0ull;

    {
        float4 av0 = *(const float4*)(Ap);
        float4 av1 = *(const float4*)(Ap + 4);
        As[0][acol+0][arow] = av0.x;
        As[0][acol+1][arow] = av0.y;
        As[0][acol+2][arow] = av0.z;
        As[0][acol+3][arow] = av0.w;
        As[0][acol+4][arow] = av1.x;
        As[0][acol+5][arow] = av1.y;
        As[0][acol+6][arow] = av1.z;
        As[0][acol+7][arow] = av1.w;
        cp_async16(bdst0,      Bp);
        cp_async16(bdst0 + 16, Bp + 4);
        cp_commit();
        cp_wait0();
    }
    __syncthreads();

    int buf = 0;
    for (int k0 = 16; k0 <= K; k0 += 16) {
        const bool more = (k0 < K);
        float4 av0, av1;
        if (more) {
            av0 = *(const float4*)(Ap + k0);
            av1 = *(const float4*)(Ap + k0 + 4);
            uint32_t bd = buf ? bdst0 : bdst1;
            const float* bsrc = Bp + (size_t)k0 * Nn;
            cp_async16(bd,      bsrc);
            cp_async16(bd + 16, bsrc + 4);
            cp_commit();
        }
        const float (*Asb)[132] = As[buf];
        const float (*Bsb)[128] = Bs[buf];
#pragma unroll
        for (int kk = 0; kk < 16; kk++) {
            float a[8];
            *(float4*)(a)   = *(const float4*)&Asb[kk][ty*8];
            *(float4*)(a+4) = *(const float4*)&Asb[kk][ty*8+4];
            ulonglong2 bp0 = *(const ulonglong2*)&Bsb[kk][tx*4];
            ulonglong2 bp1 = *(const ulonglong2*)&Bsb[kk][64 + tx*4];
            u64 b2[4] = { bp0.x, bp0.y, bp1.x, bp1.y };
#pragma unroll
            for (int i = 0; i < 8; i++) {
                u64 ad = dup2(a[i]);
#pragma unroll
                for (int j = 0; j < 4; j++)
                    acc[i][j] = fma2(ad, b2[j], acc[i][j]);
            }
        }
        if (more) {
            const int nb = buf ^ 1;
            As[nb][acol+0][arow] = av0.x;
            As[nb][acol+1][arow] = av0.y;
            As[nb][acol+2][arow] = av0.z;
            As[nb][acol+3][arow] = av0.w;
            As[nb][acol+4][arow] = av1.x;
            As[nb][acol+5][arow] = av1.y;
            As[nb][acol+6][arow] = av1.z;
            As[nb][acol+7][arow] = av1.w;
            cp_wait0();
            __syncthreads();
            buf = nb;
        }
    }

    const int crow0 = by * 128 + ty * 8;
    const int c0 = bx * 128 + tx * 4;
#pragma unroll
    for (int i = 0; i < 8; i++) {
        size_t rbase = (size_t)(crow0 + i) * Nn;
#pragma unroll
        for (int g = 0; g < 2; g++) {
            const int col = c0 + g * 64;
            float2 p0 = unpack2(acc[i][g*2 + 0]);
            float2 p1 = unpack2(acc[i][g*2 + 1]);
            float4 o;
            o.x = p0.x; o.y = p0.y; o.z = p1.x; o.w = p1.y;
            *(float4*)(C + rbase + col) = o;
        }
    }
}

// ---------------- Temporal attention (folded form) -------------------------
#define HP_ 260
__global__ void __launch_bounds__(256) attn_kernel(
    const float* __restrict__ qp, const float* __restrict__ h,
    const float* __restrict__ u, float* __restrict__ out) {
    extern __shared__ float smf[];
    float* q_s = smf;                 // [20][260]  (q' + u)
    float* h_s = smf + T_*HP_;        // [20][260]
    float* s_s = smf + 2*T_*HP_;      // [20][20]

    const int bn = blockIdx.x;
    const int n = bn >> 6, b = bn & 63;
    const size_t row0 = (size_t)n * BT_ + (size_t)b * T_;
    const int tid = threadIdx.x;
    const int wid = tid >> 5, lane = tid & 31;

    for (int idx = tid; idx < T_ * (H_/4); idx += 256) {
        int t = idx >> 6, hc = idx & 63;
        float4 qv = ((const float4*)(qp + (row0 + t) * H_))[hc];
        float4 uu = ((const float4*)u)[hc];
        qv.x += uu.x; qv.y += uu.y; qv.z += uu.z; qv.w += uu.w;
        *(float4*)(q_s + t * HP_ + hc * 4) = qv;
        *(float4*)(h_s + t * HP_ + hc * 4) =
            ((const float4*)(h + (row0 + t) * H_))[hc];
    }
    __syncthreads();

    for (int p = tid; p < T_*T_; p += 256) {
        int t = p / T_, s = p - t * T_;
        float ax = 0.f, ay = 0.f, az = 0.f, aw = 0.f;
        const float4* qq = (const float4*)(q_s + t * HP_);
        const float4* hh = (const float4*)(h_s + s * HP_);
#pragma unroll 8
        for (int hc = 0; hc < H_/4; hc++) {
            float4 qv = qq[hc];
            float4 hv = hh[hc];
            ax = fmaf(qv.x, hv.x, ax);
            ay = fmaf(qv.y, hv.y, ay);
            az = fmaf(qv.z, hv.z, az);
            aw = fmaf(qv.w, hv.w, aw);
        }
        s_s[t*T_ + s] = (ax + ay + az + aw) * 0.0625f;   // 1/sqrt(256)
    }
    __syncthreads();

    for (int t = wid; t < T_; t += 8) {
        float v = (lane < T_) ? s_s[t*T_ + lane] : -1e30f;
        float mx = v;
#pragma unroll
        for (int off = 16; off; off >>= 1)
            mx = fmaxf(mx, __shfl_xor_sync(0xffffffffu, mx, off));
        float e = (lane < T_) ? __expf(v - mx) : 0.f;
        float sum = e;
#pragma unroll
        for (int off = 16; off; off >>= 1)
            sum += __shfl_xor_sync(0xffffffffu, sum, off);
        if (lane < T_) s_s[t*T_ + lane] = e / sum;
    }
    __syncthreads();

    for (int idx = tid; idx < T_ * (H_/4); idx += 256) {
        int t = idx >> 6, hc = idx & 63;
        float4 acc = make_float4(0.f, 0.f, 0.f, 0.f);
#pragma unroll
        for (int s = 0; s < T_; s++) {
            float p = s_s[t*T_ + s];
            float4 hv = *(const float4*)(h_s + s * HP_ + hc * 4);
            acc.x = fmaf(p, hv.x, acc.x);
            acc.y = fmaf(p, hv.y, acc.y);
            acc.z = fmaf(p, hv.z, acc.z);
            acc.w = fmaf(p, hv.w, acc.w);
        }
        ((float4*)(out + (row0 + t) * H_))[hc] = acc;
    }
}

// ---------------- host launcher -------------------------------------------
extern "C" void kernel_launch(void* const* d_in, const int* in_sizes, int n_in,
                              void* d_out, int out_size) {
    const float* x     = (const float*)d_in[0];
    const float* adj   = (const float*)d_in[1];
    const float* W0    = (const float*)d_in[2];
    const float* b0    = (const float*)d_in[3];
    const float* W1    = (const float*)d_in[4];
    const float* b1    = (const float*)d_in[5];
    const float* W2    = (const float*)d_in[6];
    const float* b2    = (const float*)d_in[7];
    const float* Wq    = (const float*)d_in[8];
    const float* bq    = (const float*)d_in[9];
    const float* Wk    = (const float*)d_in[10];
    const float* bk    = (const float*)d_in[11];  // t-const in softmax: drops
    const float* Wv    = (const float*)d_in[12];
    const float* bv    = (const float*)d_in[13];
    const float* Wp    = (const float*)d_in[14];
    const float* bp    = (const float*)d_in[15];
    const float* gamma = (const float*)d_in[16];
    const float* beta  = (const float*)d_in[17];
    float* outp = (float*)d_out;
    (void)bk;

    float *m, *h0, *h1, *qv, *adjp, *wkt, *mqk, *wvp, *u, *bvp;
    cudaGetSymbolAddress((void**)&m,    g_m);
    cudaGetSymbolAddress((void**)&h0,   g_h0);
    cudaGetSymbolAddress((void**)&h1,   g_h1);
    cudaGetSymbolAddress((void**)&qv,   g_qv);
    cudaGetSymbolAddress((void**)&adjp, g_adjp);
    cudaGetSymbolAddress((void**)&wkt,  g_wkt);
    cudaGetSymbolAddress((void**)&mqk,  g_mqk);
    cudaGetSymbolAddress((void**)&wvp,  g_wvp);
    cudaGetSymbolAddress((void**)&u,    g_u);
    cudaGetSymbolAddress((void**)&bvp,  g_bvp);

    const int attn_smem = (2*T_*HP_ + T_*T_) * sizeof(float);  // 43200 B
    cudaFuncSetAttribute(attn_kernel, cudaFuncAttributeMaxDynamicSharedMemorySize,
                         attn_smem);
    cudaFuncSetAttribute(dgemm_kernel<true,true,false,false>,
        cudaFuncAttributeMaxDynamicSharedMemorySize, DSMEM);
    cudaFuncSetAttribute(dgemm_kernel<true,true,true,false>,
        cudaFuncAttributeMaxDynamicSharedMemorySize, DSMEM);
    cudaFuncSetAttribute(dgemm_kernel<false,false,false,false>,
        cudaFuncAttributeMaxDynamicSharedMemorySize, DSMEM);
    cudaFuncSetAttribute(dgemm_kernel<true,false,false,true>,
        cudaFuncAttributeMaxDynamicSharedMemorySize, DSMEM);

    // ---- prep ----
    prep_misc<<<345, 256>>>(adj, Wk, bq, bv, Wp, bp, adjp, wkt, u, bvp);
    prep_gemm<<<dim3(2, 2, 2), 256>>>(Wq, wkt, Wv, Wp, mqk, wvp);

    // ---- GCN stack (msg GEMMs use K=112 zero-padded; layer0 reads x raw) --
    sgemm_kernel<true, true><<<BT_*F_/128, 128>>>(
        adjp, x, m, NP_, BT_*F_, KP_, N_);
    dgemm_kernel<true,true,false,false><<<1000, 256, DSMEM>>>(
        m, W0, b0, nullptr, nullptr, nullptr, h0, F_);

    sgemm_kernel<true, false><<<BT_*H_/128, 128>>>(
        adjp, h0, m, NP_, BT_*H_, KP_, N_);
    dgemm_kernel<true,true,true,false><<<1000, 256, DSMEM>>>(
        m, W1, b1, h0, nullptr, nullptr, h1, H_);

    sgemm_kernel<true, false><<<BT_*H_/128, 128>>>(
        adjp, h1, m, NP_, BT_*H_, KP_, N_);
    dgemm_kernel<true,true,true,false><<<1000, 256, DSMEM>>>(
        m, W2, b2, h1, nullptr, nullptr, h0, H_);

    // ---- folded attention path ----
    dgemm_kernel<false,false,false,false><<<1000, 256, DSMEM>>>(
        h0, mqk, nullptr, nullptr, nullptr, nullptr, qv, H_);

    attn_kernel<<<N_*B_, 256, attn_smem>>>(qv, h0, u, m);

    // final projection + fused LayerNorm + scatter to [b,t,n,h]
    dgemm_kernel<true,false,false,true><<<1000, 256, DSMEM>>>(
        m, wvp, bvp, nullptr, gamma, beta, outp, H_);
}